// round 2
// baseline (speedup 1.0000x reference)
#include <cuda_runtime.h>

// ---------------- problem constants (fixed by the dataset) ----------------
#define NA    4096
#define NB    4000
#define NANG  8000
#define NAC   4000
#define ND    12000
#define NDC   6000
#define NI    2000
#define TILE  128
#define NTILE (NA / TILE)                    // 32
#define NPAIRBLK (NTILE * (NTILE + 1) / 2)   // 528
#define COULF 332.33f
#define EPSF  1e-12f

#define ANG_OFF   (NB)                       // 4000
#define ANGC_OFF  (ANG_OFF + NANG)           // 12000
#define DIH_OFF   (ANGC_OFF + NAC)           // 16000
#define DIHC_OFF  (DIH_OFF + ND)             // 28000
#define IMP_OFF   (DIHC_OFF + NDC)           // 34000
#define CORR_OFF  (IMP_OFF + NI)             // 36000
#define NCORR     (NB + NANG)                // 12000
#define TOT_BONDED (CORR_OFF + NCORR)        // 48000

// ---------------- device scratch (static, allocation-free) ----------------
__device__ double       g_acc;
__device__ float4       g_posq[NA];               // x,y,z, q*sqrt(COULOMB)
__device__ float2       g_ls[NA];                 // 0.5*sigma, 2*sqrt(eps)
__device__ unsigned int g_flags[NA * NA / 32];    // 2 MB dedup bitmap (zero-init; re-cleared each call)

// ---------------- math helpers ----------------
__device__ __forceinline__ float rsqrt_fast(float x) {
    // FFMA-only rsqrt: avoids the MUFU pipe (rt_SMSP=8 would bottleneck 8.4M calls)
    float y = __uint_as_float(0x5f375a86u - (__float_as_uint(x) >> 1));
    float xh = 0.5f * x;
    y = y * (1.5f - xh * y * y);
    y = y * (1.5f - xh * y * y);
    return y;
}

struct f3 { float x, y, z; };
__device__ __forceinline__ f3 ldp(const float* p, int i) {
    return { p[3 * i], p[3 * i + 1], p[3 * i + 2] };
}
__device__ __forceinline__ f3 f3sub(f3 a, f3 b) { return { a.x - b.x, a.y - b.y, a.z - b.z }; }
__device__ __forceinline__ float f3dot(f3 a, f3 b) { return a.x * b.x + a.y * b.y + a.z * b.z; }
__device__ __forceinline__ f3 f3cross(f3 a, f3 b) {
    return { a.y * b.z - a.z * b.y, a.z * b.x - a.x * b.z, a.x * b.y - a.y * b.x };
}

__device__ __forceinline__ float angle3(f3 p0, f3 p1, f3 p2) {
    f3 u = f3sub(p0, p1);
    f3 v = f3sub(p2, p1);
    float c = f3dot(u, v) / sqrtf(f3dot(u, u) * f3dot(v, v) + EPSF);
    c = fminf(fmaxf(c, -1.0f + 1e-7f), 1.0f - 1e-7f);
    return acosf(c);
}

__device__ __forceinline__ float dihedral_phi(f3 p0, f3 p1, f3 p2, f3 p3) {
    f3 b1 = f3sub(p1, p0);
    f3 b2 = f3sub(p2, p1);
    f3 b3 = f3sub(p3, p2);
    f3 n1 = f3cross(b1, b2);
    f3 n2 = f3cross(b2, b3);
    float bl = sqrtf(f3dot(b2, b2) + EPSF);
    f3 b2n = { b2.x / bl, b2.y / bl, b2.z / bl };
    float yv = f3dot(f3cross(n1, b2n), n2);
    float xv = f3dot(n1, n2);
    return atan2f(yv, xv);
}

// LJ + Coulomb pair energy from precomputed per-atom data (same formula as main loop)
__device__ __forceinline__ float pair_energy(int i, int j) {
    float4 a = g_posq[i], b = g_posq[j];
    float2 la = g_ls[i],  lb = g_ls[j];
    float dx = a.x - b.x, dy = a.y - b.y, dz = a.z - b.z;
    float r2 = fmaf(dx, dx, fmaf(dy, dy, fmaf(dz, dz, EPSF)));
    float rinv = rsqrt_fast(r2);
    float s  = la.x + lb.x;
    float s2 = s * s;
    float s6 = s2 * s2 * s2;
    float ri2 = rinv * rinv;
    float ri6 = ri2 * ri2 * ri2;
    float sr6 = s6 * ri6;
    return la.y * lb.y * sr6 * (sr6 - 1.0f) + a.w * b.w * rinv;
}

// ---------------- kernel 1: init accumulator + per-atom derived data ----------------
__global__ void k_init(const float* __restrict__ pos, const float* __restrict__ q,
                       const float* __restrict__ eps, const float* __restrict__ sig) {
    int i = blockIdx.x * blockDim.x + threadIdx.x;
    if (i == 0) g_acc = 0.0;
    if (i < NA) {
        g_posq[i] = make_float4(pos[3 * i], pos[3 * i + 1], pos[3 * i + 2],
                                q[i] * sqrtf(COULF));
        g_ls[i] = make_float2(0.5f * sig[i], 2.0f * sqrtf(eps[i]));
    }
}

// ---------------- kernel 2: all-pairs LJ + Coulomb (mask assumed 1 everywhere) ----------------
__global__ void __launch_bounds__(TILE) k_pairs() {
    __shared__ float4 spq[TILE];
    __shared__ float2 sls[TILE];

    // decode linear block id -> (bi, bj) with bi <= bj  (upper-triangle tile enumeration)
    int t = blockIdx.x;
    int bi = 0, rowlen = NTILE;
    while (t >= rowlen) { t -= rowlen; rowlen--; bi++; }
    int bj = bi + t;

    int li = threadIdx.x;
    int gi = bi * TILE + li;
    float4 pqi = g_posq[gi];
    float2 lsi = g_ls[gi];

    int gj0 = bj * TILE;
    spq[li] = g_posq[gj0 + li];
    sls[li] = g_ls[gj0 + li];
    __syncthreads();

    const bool diag = (bi == bj);
    float acc = 0.0f;

#pragma unroll 8
    for (int j = 0; j < TILE; j++) {
        float4 pqj = spq[j];
        float2 lsj = sls[j];
        float dx = pqi.x - pqj.x;
        float dy = pqi.y - pqj.y;
        float dz = pqi.z - pqj.z;
        float r2 = fmaf(dx, dx, fmaf(dy, dy, fmaf(dz, dz, EPSF)));
        bool valid = (!diag) || (j > li);
        r2 = valid ? r2 : 1.0f;          // keep math finite on skipped lanes
        float rinv = rsqrt_fast(r2);
        float s  = lsi.x + lsj.x;
        float s2 = s * s;
        float s6 = s2 * s2 * s2;
        float ri2 = rinv * rinv;
        float ri6 = ri2 * ri2 * ri2;
        float sr6 = s6 * ri6;
        float e = lsi.y * lsj.y * sr6 * (sr6 - 1.0f) + pqi.w * pqj.w * rinv;
        acc += valid ? e : 0.0f;
    }

    // warp reduce, then block reduce in double, one atomic per block
    for (int off = 16; off; off >>= 1)
        acc += __shfl_down_sync(0xffffffffu, acc, off);
    __shared__ float wsum[TILE / 32];
    if ((threadIdx.x & 31) == 0) wsum[threadIdx.x >> 5] = acc;
    __syncthreads();
    if (threadIdx.x == 0) {
        double s = 0.0;
#pragma unroll
        for (int w = 0; w < TILE / 32; w++) s += (double)wsum[w];
        atomicAdd(&g_acc, s);
    }
}

// ---------------- kernel 3: all bonded terms + mask correction ----------------
// NOTE: all index arrays are int32 — JAX (x64 disabled) downcasts the numpy
// int64 arrays on jnp.asarray. Reading them as int64 was the R1 crash.
__global__ void __launch_bounds__(256) k_bonded(
    const float* __restrict__ pos,
    const float* __restrict__ sb_mask,
    const float* __restrict__ bond_c,   // [NT,2]
    const float* __restrict__ angle_c,  // [NT,2]
    const float* __restrict__ anglec_c, // [NT,4]
    const float* __restrict__ dih_c,    // [NT,5]
    const float* __restrict__ dihc_c,   // [NT,4]
    const float* __restrict__ imp_c,    // [NT,2]
    const int* __restrict__ bond_i,     // [NB,3]
    const int* __restrict__ angle_i,    // [NANG,4]
    const int* __restrict__ anglec_i,   // [NAC,4]
    const int* __restrict__ dih_i,      // [ND,5]
    const int* __restrict__ dihc_i,     // [NDC,5]
    const int* __restrict__ imp_i)      // [NI,5]
{
    int gid = blockIdx.x * blockDim.x + threadIdx.x;
    float e = 0.0f;

    if (gid < ANG_OFF) {
        // bonds
        const int* b = bond_i + 3 * gid;
        int i = b[0], j = b[1], ty = b[2];
        f3 pi = ldp(pos, i), pj = ldp(pos, j);
        f3 d = f3sub(pi, pj);
        float r = sqrtf(f3dot(d, d) + EPSF);
        float dr = r - bond_c[2 * ty + 1];
        e = bond_c[2 * ty] * dr * dr;
    } else if (gid < ANGC_OFF) {
        // harmonic angles
        int k = gid - ANG_OFF;
        const int* a = angle_i + 4 * k;
        int ty = a[3];
        float th = angle3(ldp(pos, a[0]), ldp(pos, a[1]), ldp(pos, a[2]));
        float dth = th - angle_c[2 * ty + 1];
        e = angle_c[2 * ty] * dth * dth;
    } else if (gid < DIH_OFF) {
        // CHARMM angles (+ Urey-Bradley 1-3 term)
        int k = gid - ANGC_OFF;
        const int* a = anglec_i + 4 * k;
        int ty = a[3];
        f3 p0 = ldp(pos, a[0]), p1 = ldp(pos, a[1]), p2 = ldp(pos, a[2]);
        float th = angle3(p0, p1, p2);
        f3 d02 = f3sub(p0, p2);
        float r13 = sqrtf(f3dot(d02, d02) + EPSF);
        const float* c = anglec_c + 4 * ty;
        float dth = th - c[1];
        float dr  = r13 - c[3];
        e = c[0] * dth * dth + c[2] * dr * dr;
    } else if (gid < DIHC_OFF) {
        // OPLS-style dihedral polynomial in cos(phi)
        int k = gid - DIH_OFF;
        const int* a = dih_i + 5 * k;
        int ty = a[4];
        float phi = dihedral_phi(ldp(pos, a[0]), ldp(pos, a[1]),
                                 ldp(pos, a[2]), ldp(pos, a[3]));
        float c = cosf(phi);
        const float* A = dih_c + 5 * ty;
        e = A[0] + c * (A[1] + c * (A[2] + c * (A[3] + c * A[4])));
    } else if (gid < IMP_OFF) {
        // CHARMM dihedral
        int k = gid - DIHC_OFF;
        const int* a = dihc_i + 5 * k;
        int ty = a[4];
        float phi = dihedral_phi(ldp(pos, a[0]), ldp(pos, a[1]),
                                 ldp(pos, a[2]), ldp(pos, a[3]));
        const float* c = dihc_c + 4 * ty;
        e = c[0] * (1.0f + cosf(c[1] * phi - c[2]));
    } else if (gid < CORR_OFF) {
        // impropers
        int k = gid - IMP_OFF;
        const int* a = imp_i + 5 * k;
        int ty = a[4];
        float chi = dihedral_phi(ldp(pos, a[0]), ldp(pos, a[1]),
                                 ldp(pos, a[2]), ldp(pos, a[3]));
        float d = chi - imp_c[2 * ty + 1];
        e = imp_c[2 * ty] * d * d;
    } else if (gid < TOT_BONDED) {
        // mask==0 correction: only bond pairs and angle-1-3 pairs can be masked out.
        // Subtract their (already-summed) pair energy exactly once per distinct pair.
        int c = gid - CORR_OFF;
        int iu, iv;
        if (c < NB) { iu = bond_i[3 * c]; iv = bond_i[3 * c + 1]; }
        else        { int a = c - NB; iu = angle_i[4 * a]; iv = angle_i[4 * a + 2]; }
        if (iu != iv) {
            int lo = min(iu, iv), hi = max(iu, iv);
            float m = sb_mask[(size_t)lo * NA + hi];
            if (m == 0.0f) {
                unsigned key = (unsigned)lo * NA + (unsigned)hi;
                unsigned bit = 1u << (key & 31u);
                unsigned old = atomicOr(&g_flags[key >> 5], bit);
                if (!(old & bit)) e = -pair_energy(lo, hi);
            }
        }
    }

    // block reduce -> one double atomic per block
    for (int off = 16; off; off >>= 1)
        e += __shfl_down_sync(0xffffffffu, e, off);
    __shared__ float wsum[8];
    if ((threadIdx.x & 31) == 0) wsum[threadIdx.x >> 5] = e;
    __syncthreads();
    if (threadIdx.x == 0) {
        double s = 0.0;
#pragma unroll
        for (int w = 0; w < 8; w++) s += (double)wsum[w];
        atomicAdd(&g_acc, s);
    }
}

// ---------------- kernel 4: clear dedup bitmap + emit result ----------------
__global__ void k_final(float* __restrict__ out,
                        const int* __restrict__ bond_i,
                        const int* __restrict__ angle_i) {
    int gid = blockIdx.x * blockDim.x + threadIdx.x;
    if (gid < NCORR) {
        int iu, iv;
        if (gid < NB) { iu = bond_i[3 * gid]; iv = bond_i[3 * gid + 1]; }
        else          { int a = gid - NB; iu = angle_i[4 * a]; iv = angle_i[4 * a + 2]; }
        if (iu != iv) {
            int lo = min(iu, iv), hi = max(iu, iv);
            unsigned key = (unsigned)lo * NA + (unsigned)hi;
            g_flags[key >> 5] = 0u;   // benign race: every writer stores 0
        }
    }
    if (blockIdx.x == 0 && threadIdx.x == 0) out[0] = (float)g_acc;
}

// ---------------- launch ----------------
extern "C" void kernel_launch(void* const* d_in, const int* in_sizes, int n_in,
                              void* d_out, int out_size) {
    const float* atom_pos    = (const float*)d_in[0];
    const float* atom_charge = (const float*)d_in[1];
    const float* epsilon     = (const float*)d_in[2];
    const float* sigma       = (const float*)d_in[3];
    const float* sb_mask     = (const float*)d_in[4];
    const float* bond_c      = (const float*)d_in[5];
    const float* angle_c     = (const float*)d_in[6];
    const float* anglec_c    = (const float*)d_in[7];
    const float* dih_c       = (const float*)d_in[8];
    const float* dihc_c      = (const float*)d_in[9];
    const float* imp_c       = (const float*)d_in[10];
    const int* bond_i   = (const int*)d_in[11];
    const int* angle_i  = (const int*)d_in[12];
    const int* anglec_i = (const int*)d_in[13];
    const int* dih_i    = (const int*)d_in[14];
    const int* dihc_i   = (const int*)d_in[15];
    const int* imp_i    = (const int*)d_in[16];
    // d_in[17] = pair_idx: deliberately unused (it is just triu_indices(NA,1))

    k_init<<<(NA + 127) / 128, 128>>>(atom_pos, atom_charge, epsilon, sigma);
    k_pairs<<<NPAIRBLK, TILE>>>();
    k_bonded<<<(TOT_BONDED + 255) / 256, 256>>>(
        atom_pos, sb_mask, bond_c, angle_c, anglec_c, dih_c, dihc_c, imp_c,
        bond_i, angle_i, anglec_i, dih_i, dihc_i, imp_i);
    k_final<<<(NCORR + 255) / 256, 256>>>((float*)d_out, bond_i, angle_i);
}

// round 3
// speedup vs baseline: 1.1420x; 1.1420x over previous
#include <cuda_runtime.h>

// ---------------- problem constants (fixed by the dataset) ----------------
#define NA    4096
#define NB    4000
#define NANG  8000
#define NAC   4000
#define ND    12000
#define NDC   6000
#define NI    2000
#define TILE  128
#define NTILE (NA / TILE)                    // 32
#define NPAIRBLK (NTILE * (NTILE + 1) / 2)   // 528
#define COULF 332.33f
#define EPSF  1e-12f

#define ANG_OFF   (NB)                       // 4000
#define ANGC_OFF  (ANG_OFF + NANG)           // 12000
#define DIH_OFF   (ANGC_OFF + NAC)           // 16000
#define DIHC_OFF  (DIH_OFF + ND)             // 28000
#define IMP_OFF   (DIHC_OFF + NDC)           // 34000
#define CORR_OFF  (IMP_OFF + NI)             // 36000
#define NCORR     (NB + NANG)                // 12000
#define TOT_BONDED (CORR_OFF + NCORR)        // 48000
#define NBONDBLK  ((TOT_BONDED + TILE - 1) / TILE)  // 375
#define NBLK_MAIN (NPAIRBLK + NBONDBLK)             // 903

#define HASH_BITS 15
#define HASH_SIZE (1 << HASH_BITS)           // 32768 entries, ~12000 used

// ---------------- device scratch (static, allocation-free) ----------------
__device__ double       g_acc;
__device__ float4       g_posq[NA];          // x,y,z, q*sqrt(COULOMB)
__device__ float2       g_ls[NA];            // 0.5*sigma, 2*sqrt(eps)
__device__ unsigned int g_hash[HASH_SIZE];   // dedup hash set, cleared each call in k_init

// ---------------- math helpers ----------------
__device__ __forceinline__ float rsqrt_mufu(float x) {
    // single MUFU.RSQ (rt_SMSP=8 -> chip-wide ~74 warp-instr/cyc, never binding
    // at 270k warp-rsqrts) + one Newton step to recover full fp32 accuracy
    // (error^2: 2^-22 -> negligible even after the ^12 LJ amplification).
    float y;
    asm("rsqrt.approx.f32 %0, %1;" : "=f"(y) : "f"(x));
    return y * fmaf(-0.5f * x, y * y, 1.5f);
}

struct f3 { float x, y, z; };
__device__ __forceinline__ f3 ldp(const float* p, int i) {
    return { p[3 * i], p[3 * i + 1], p[3 * i + 2] };
}
__device__ __forceinline__ f3 f3sub(f3 a, f3 b) { return { a.x - b.x, a.y - b.y, a.z - b.z }; }
__device__ __forceinline__ float f3dot(f3 a, f3 b) { return a.x * b.x + a.y * b.y + a.z * b.z; }
__device__ __forceinline__ f3 f3cross(f3 a, f3 b) {
    return { a.y * b.z - a.z * b.y, a.z * b.x - a.x * b.z, a.x * b.y - a.y * b.x };
}

__device__ __forceinline__ float angle3(f3 p0, f3 p1, f3 p2) {
    f3 u = f3sub(p0, p1);
    f3 v = f3sub(p2, p1);
    float c = f3dot(u, v) / sqrtf(f3dot(u, u) * f3dot(v, v) + EPSF);
    c = fminf(fmaxf(c, -1.0f + 1e-7f), 1.0f - 1e-7f);
    return acosf(c);
}

__device__ __forceinline__ float dihedral_phi(f3 p0, f3 p1, f3 p2, f3 p3) {
    f3 b1 = f3sub(p1, p0);
    f3 b2 = f3sub(p2, p1);
    f3 b3 = f3sub(p3, p2);
    f3 n1 = f3cross(b1, b2);
    f3 n2 = f3cross(b2, b3);
    float bl = sqrtf(f3dot(b2, b2) + EPSF);
    f3 b2n = { b2.x / bl, b2.y / bl, b2.z / bl };
    float yv = f3dot(f3cross(n1, b2n), n2);
    float xv = f3dot(n1, n2);
    return atan2f(yv, xv);
}

// LJ + Coulomb pair energy (must match the main pair loop bit-for-bit in structure)
__device__ __forceinline__ float pair_energy(int i, int j) {
    float4 a = g_posq[i], b = g_posq[j];
    float2 la = g_ls[i],  lb = g_ls[j];
    float dx = a.x - b.x, dy = a.y - b.y, dz = a.z - b.z;
    float r2 = fmaf(dx, dx, fmaf(dy, dy, fmaf(dz, dz, EPSF)));
    float rinv = rsqrt_mufu(r2);
    float sr  = (la.x + lb.x) * rinv;
    float sr2 = sr * sr;
    float sr6 = sr2 * sr2 * sr2;
    float t   = fmaf(sr6, sr6, -sr6);        // sr12 - sr6
    return fmaf(la.y * lb.y, t, a.w * b.w * rinv);
}

// ---------------- kernel 1: init accumulator, per-atom data, clear hash ----------------
__global__ void k_init(const float* __restrict__ pos, const float* __restrict__ q,
                       const float* __restrict__ eps, const float* __restrict__ sig) {
    int i = blockIdx.x * blockDim.x + threadIdx.x;   // 0..4095
    if (i == 0) g_acc = 0.0;
    if (i < NA) {
        g_posq[i] = make_float4(pos[3 * i], pos[3 * i + 1], pos[3 * i + 2],
                                q[i] * sqrtf(COULF));
        g_ls[i] = make_float2(0.5f * sig[i], 2.0f * sqrtf(eps[i]));
    }
#pragma unroll
    for (int k = 0; k < HASH_SIZE / NA; k++)         // 8 sequential stores/thread
        g_hash[i + k * NA] = 0u;
}

// ---------------- bonded + correction block body ----------------
__device__ __forceinline__ void bonded_body(
    int gid,
    const float* __restrict__ pos,
    const float* __restrict__ sb_mask,
    const float* __restrict__ bond_c, const float* __restrict__ angle_c,
    const float* __restrict__ anglec_c, const float* __restrict__ dih_c,
    const float* __restrict__ dihc_c, const float* __restrict__ imp_c,
    const int* __restrict__ bond_i, const int* __restrict__ angle_i,
    const int* __restrict__ anglec_i, const int* __restrict__ dih_i,
    const int* __restrict__ dihc_i, const int* __restrict__ imp_i,
    float& e)
{
    if (gid < ANG_OFF) {
        const int* b = bond_i + 3 * gid;
        int i = b[0], j = b[1], ty = b[2];
        f3 d = f3sub(ldp(pos, i), ldp(pos, j));
        float r = sqrtf(f3dot(d, d) + EPSF);
        float dr = r - bond_c[2 * ty + 1];
        e = bond_c[2 * ty] * dr * dr;
    } else if (gid < ANGC_OFF) {
        int k = gid - ANG_OFF;
        const int* a = angle_i + 4 * k;
        int ty = a[3];
        float th = angle3(ldp(pos, a[0]), ldp(pos, a[1]), ldp(pos, a[2]));
        float dth = th - angle_c[2 * ty + 1];
        e = angle_c[2 * ty] * dth * dth;
    } else if (gid < DIH_OFF) {
        int k = gid - ANGC_OFF;
        const int* a = anglec_i + 4 * k;
        int ty = a[3];
        f3 p0 = ldp(pos, a[0]), p1 = ldp(pos, a[1]), p2 = ldp(pos, a[2]);
        float th = angle3(p0, p1, p2);
        f3 d02 = f3sub(p0, p2);
        float r13 = sqrtf(f3dot(d02, d02) + EPSF);
        const float* c = anglec_c + 4 * ty;
        float dth = th - c[1];
        float dr  = r13 - c[3];
        e = c[0] * dth * dth + c[2] * dr * dr;
    } else if (gid < DIHC_OFF) {
        int k = gid - DIH_OFF;
        const int* a = dih_i + 5 * k;
        int ty = a[4];
        float phi = dihedral_phi(ldp(pos, a[0]), ldp(pos, a[1]),
                                 ldp(pos, a[2]), ldp(pos, a[3]));
        float c = cosf(phi);
        const float* A = dih_c + 5 * ty;
        e = A[0] + c * (A[1] + c * (A[2] + c * (A[3] + c * A[4])));
    } else if (gid < IMP_OFF) {
        int k = gid - DIHC_OFF;
        const int* a = dihc_i + 5 * k;
        int ty = a[4];
        float phi = dihedral_phi(ldp(pos, a[0]), ldp(pos, a[1]),
                                 ldp(pos, a[2]), ldp(pos, a[3]));
        const float* c = dihc_c + 4 * ty;
        e = c[0] * (1.0f + cosf(c[1] * phi - c[2]));
    } else if (gid < CORR_OFF) {
        int k = gid - IMP_OFF;
        const int* a = imp_i + 5 * k;
        int ty = a[4];
        float chi = dihedral_phi(ldp(pos, a[0]), ldp(pos, a[1]),
                                 ldp(pos, a[2]), ldp(pos, a[3]));
        float d = chi - imp_c[2 * ty + 1];
        e = imp_c[2 * ty] * d * d;
    } else if (gid < TOT_BONDED) {
        // mask==0 correction: candidates = bond pairs + angle 1-3 pairs.
        // Subtract each distinct masked pair's energy exactly once (hash-set dedup).
        int c = gid - CORR_OFF;
        int iu, iv;
        if (c < NB) { iu = bond_i[3 * c]; iv = bond_i[3 * c + 1]; }
        else        { int a = c - NB; iu = angle_i[4 * a]; iv = angle_i[4 * a + 2]; }
        if (iu != iv) {
            int lo = min(iu, iv), hi = max(iu, iv);
            if (sb_mask[(size_t)lo * NA + hi] == 0.0f) {
                unsigned key = ((unsigned)lo << 12) | (unsigned)hi;   // nonzero (lo<hi)
                unsigned h = (key * 2654435761u) >> (32 - HASH_BITS);
                bool first = false;
                for (;;) {
                    unsigned old = atomicCAS(&g_hash[h], 0u, key);
                    if (old == 0u) { first = true; break; }
                    if (old == key) break;
                    h = (h + 1) & (HASH_SIZE - 1);
                }
                if (first) e = -pair_energy(lo, hi);
            }
        }
    }
}

// ---------------- kernel 2: pairs (blocks 0..527) + bonded (blocks 528..902) ----------------
__global__ void __launch_bounds__(TILE) k_main(
    const float* __restrict__ pos,
    const float* __restrict__ sb_mask,
    const float* __restrict__ bond_c, const float* __restrict__ angle_c,
    const float* __restrict__ anglec_c, const float* __restrict__ dih_c,
    const float* __restrict__ dihc_c, const float* __restrict__ imp_c,
    const int* __restrict__ bond_i, const int* __restrict__ angle_i,
    const int* __restrict__ anglec_i, const int* __restrict__ dih_i,
    const int* __restrict__ dihc_i, const int* __restrict__ imp_i)
{
    float acc = 0.0f;

    if (blockIdx.x < NPAIRBLK) {
        // ---- all-pairs LJ + Coulomb over one 128x128 tile ----
        __shared__ float4 spq[TILE];
        __shared__ float2 sls[TILE];

        int t = blockIdx.x;
        int bi = 0, rowlen = NTILE;
        while (t >= rowlen) { t -= rowlen; rowlen--; bi++; }
        int bj = bi + t;

        int li = threadIdx.x;
        float4 pqi = g_posq[bi * TILE + li];
        float2 lsi = g_ls[bi * TILE + li];

        spq[li] = g_posq[bj * TILE + li];
        sls[li] = g_ls[bj * TILE + li];
        __syncthreads();

        const bool diag = (bi == bj);

#pragma unroll 8
        for (int j = 0; j < TILE; j++) {
            float4 pqj = spq[j];
            float2 lsj = sls[j];
            float dx = pqi.x - pqj.x;
            float dy = pqi.y - pqj.y;
            float dz = pqi.z - pqj.z;
            float r2 = fmaf(dx, dx, fmaf(dy, dy, fmaf(dz, dz, EPSF)));
            bool valid = (!diag) || (j > li);
            r2 = valid ? r2 : 1.0f;                  // keep math finite on skipped lanes
            float rinv = rsqrt_mufu(r2);
            float sr  = (lsi.x + lsj.x) * rinv;
            float sr2 = sr * sr;
            float sr6 = sr2 * sr2 * sr2;
            float tt  = fmaf(sr6, sr6, -sr6);        // sr12 - sr6
            float e   = fmaf(lsi.y * lsj.y, tt, pqi.w * pqj.w * rinv);
            acc += valid ? e : 0.0f;
        }
    } else {
        // ---- bonded terms + mask correction ----
        int gid = (blockIdx.x - NPAIRBLK) * TILE + threadIdx.x;
        bonded_body(gid, pos, sb_mask, bond_c, angle_c, anglec_c, dih_c, dihc_c,
                    imp_c, bond_i, angle_i, anglec_i, dih_i, dihc_i, imp_i, acc);
    }

    // block reduce -> one double atomic per block
    for (int off = 16; off; off >>= 1)
        acc += __shfl_down_sync(0xffffffffu, acc, off);
    __shared__ float wsum[TILE / 32];
    if ((threadIdx.x & 31) == 0) wsum[threadIdx.x >> 5] = acc;
    __syncthreads();
    if (threadIdx.x == 0) {
        double s = 0.0;
#pragma unroll
        for (int w = 0; w < TILE / 32; w++) s += (double)wsum[w];
        atomicAdd(&g_acc, s);
    }
}

// ---------------- kernel 3: emit result ----------------
__global__ void k_final(float* __restrict__ out) {
    out[0] = (float)g_acc;
}

// ---------------- launch ----------------
extern "C" void kernel_launch(void* const* d_in, const int* in_sizes, int n_in,
                              void* d_out, int out_size) {
    const float* atom_pos    = (const float*)d_in[0];
    const float* atom_charge = (const float*)d_in[1];
    const float* epsilon     = (const float*)d_in[2];
    const float* sigma       = (const float*)d_in[3];
    const float* sb_mask     = (const float*)d_in[4];
    const float* bond_c      = (const float*)d_in[5];
    const float* angle_c     = (const float*)d_in[6];
    const float* anglec_c    = (const float*)d_in[7];
    const float* dih_c       = (const float*)d_in[8];
    const float* dihc_c      = (const float*)d_in[9];
    const float* imp_c       = (const float*)d_in[10];
    const int* bond_i   = (const int*)d_in[11];
    const int* angle_i  = (const int*)d_in[12];
    const int* anglec_i = (const int*)d_in[13];
    const int* dih_i    = (const int*)d_in[14];
    const int* dihc_i   = (const int*)d_in[15];
    const int* imp_i    = (const int*)d_in[16];
    // d_in[17] = pair_idx: deliberately unused (it is just triu_indices(NA,1))

    k_init<<<NA / TILE, TILE>>>(atom_pos, atom_charge, epsilon, sigma);
    k_main<<<NBLK_MAIN, TILE>>>(atom_pos, sb_mask, bond_c, angle_c, anglec_c,
                                dih_c, dihc_c, imp_c, bond_i, angle_i, anglec_i,
                                dih_i, dihc_i, imp_i);
    k_final<<<1, 1>>>((float*)d_out);
}